// round 5
// baseline (speedup 1.0000x reference)
#include <cuda_runtime.h>
#include <math.h>

#define EMB   1024
#define HS    64
#define TSEQ  4096
#define BATCH 4
#define MTOT  (BATCH * TSEQ)   // 16384 rows

#define NQT    64              // 64-row q tiles per batch
#define CHUNK  4               // kv-tiles per partial block
#define NBLK   544             // sum_{c=0..15} (64-4c) blocks per batch

// Scratch (device globals: allocation-free rule)
__device__ float g_q[MTOT * HS];
__device__ float g_k[MTOT * HS];
__device__ float g_v[MTOT * HS];
__device__ float g_po[BATCH * NBLK * 64 * HS];   // partial O (unnormalized)
__device__ float g_pm[BATCH * NBLK * 64];        // partial row max
__device__ float g_pl[BATCH * NBLK * 64];        // partial row sum

// ---------------------------------------------------------------------------
// Kernel 1: QKV projection.  Y = X @ W for W in {Wq, Wk, Wv} (blockIdx.y).
// BM=128, BN=64(=HS), BK=16. 256 threads, each computes an 8x4 microtile.
// ---------------------------------------------------------------------------
__global__ __launch_bounds__(256) void qkv_kernel(
    const float* __restrict__ X,
    const float* __restrict__ Wq,
    const float* __restrict__ Wk,
    const float* __restrict__ Wv)
{
    __shared__ float Xs[16][128];   // transposed: Xs[k][row]
    __shared__ float Ws[16][64];    // natural:    Ws[k][col]

    const float* W;
    float* Y;
    if (blockIdx.y == 0)      { W = Wq; Y = g_q; }
    else if (blockIdx.y == 1) { W = Wk; Y = g_k; }
    else                      { W = Wv; Y = g_v; }

    const int tid = threadIdx.x;
    const int tx = tid & 15;
    const int ty = tid >> 4;
    const int m0 = blockIdx.x * 128;

    const int lr = tid & 127;
    const int lc = tid >> 7;
    const int wr = tid >> 4;
    const int wc = (tid & 15) * 4;

    float acc[8][4];
#pragma unroll
    for (int i = 0; i < 8; i++)
#pragma unroll
        for (int j = 0; j < 4; j++) acc[i][j] = 0.0f;

    for (int k0 = 0; k0 < EMB; k0 += 16) {
#pragma unroll
        for (int t = 0; t < 2; t++) {
            int c4 = lc + 2 * t;
            float4 xv = *(const float4*)&X[(size_t)(m0 + lr) * EMB + k0 + 4 * c4];
            Xs[4 * c4 + 0][lr] = xv.x;
            Xs[4 * c4 + 1][lr] = xv.y;
            Xs[4 * c4 + 2][lr] = xv.z;
            Xs[4 * c4 + 3][lr] = xv.w;
        }
        *(float4*)&Ws[wr][wc] = *(const float4*)&W[(size_t)(k0 + wr) * HS + wc];
        __syncthreads();

#pragma unroll
        for (int kk = 0; kk < 16; kk++) {
            float4 a0 = *(const float4*)&Xs[kk][8 * ty];
            float4 a1 = *(const float4*)&Xs[kk][8 * ty + 4];
            float4 bv = *(const float4*)&Ws[kk][4 * tx];
            float a[8] = {a0.x, a0.y, a0.z, a0.w, a1.x, a1.y, a1.z, a1.w};
            float bb[4] = {bv.x, bv.y, bv.z, bv.w};
#pragma unroll
            for (int i = 0; i < 8; i++)
#pragma unroll
                for (int j = 0; j < 4; j++)
                    acc[i][j] = fmaf(a[i], bb[j], acc[i][j]);
        }
        __syncthreads();
    }

#pragma unroll
    for (int i = 0; i < 8; i++) {
        float4 o = make_float4(acc[i][0], acc[i][1], acc[i][2], acc[i][3]);
        *(float4*)&Y[(size_t)(m0 + 8 * ty + i) * HS + 4 * tx] = o;
    }
}

// ---------------------------------------------------------------------------
// Kernel 2: split-KV flash attention partials.
// Each block: one 64-row q-tile x up to CHUNK(=4) kv-tiles. Emits
// (O_partial unnormalized, m, l) to global scratch.
// Block map (per batch): for chunk c in 0..15, qt in [4c, 64): linear id
// l = P_c + (qt - 4c), P_c = 66c - 2c^2.  Total NBLK = 544.
// 256 threads = 16x16; each thread owns a 4x4 microtile. Inner loops are
// h-chunked by 2: broadcast LDS.64 for the a-operand, LDS.128 for b.
// ---------------------------------------------------------------------------
#define QSTRIDE 68
#define SMEM_FLOATS (64 * QSTRIDE /*Qs*/ + 64 * 64 /*Kst*/ + 64 * QSTRIDE /*Vs*/ + 64 * QSTRIDE /*Ps*/)
#define SMEM_BYTES (SMEM_FLOATS * 4)

__global__ __launch_bounds__(256) void attn_partial_kernel(void)
{
    extern __shared__ float sm[];
    float* Qs  = sm;                       // [64][68] natural
    float* Kst = Qs  + 64 * QSTRIDE;       // [64][64] transposed: Kst[h][j]
    float* Vs  = Kst + 64 * 64;            // [64][68] natural
    float* Ps  = Vs  + 64 * QSTRIDE;       // [64][68] natural

    const int b = blockIdx.y;
    const int l = blockIdx.x;

    // decode (chunk c, q-tile qt) from linear block id
    int c = 0, base = 0;
    for (;;) { int cnt = 64 - 4 * c; if (l < base + cnt) break; base += cnt; ++c; }
    const int qt  = 4 * c + (l - base);
    const int kt0 = 4 * c;
    const int kt1 = min(4 * c + CHUNK, qt + 1);

    const int tid = threadIdx.x;
    const int tx = tid & 15;
    const int ty = tid >> 4;

    const float* Qg = g_q + ((size_t)b * TSEQ + qt * 64) * HS;
    const float* Kg = g_k + (size_t)b * TSEQ * HS;
    const float* Vg = g_v + (size_t)b * TSEQ * HS;

    // ---- load Q tile (once) ----
    {
        int r  = tid & 63;
        int cb = tid >> 6;
#pragma unroll
        for (int t = 0; t < 4; t++) {
            int c4 = cb + 4 * t;
            float4 v = *(const float4*)&Qg[(size_t)r * HS + 4 * c4];
            *(float4*)&Qs[r * QSTRIDE + 4 * c4] = v;
        }
    }

    float m_[4], l_[4], o[4][4];
#pragma unroll
    for (int i = 0; i < 4; i++) {
        m_[i] = -1e30f; l_[i] = 0.0f;
#pragma unroll
        for (int j = 0; j < 4; j++) o[i][j] = 0.0f;
    }

    for (int kt = kt0; kt < kt1; kt++) {
        const float* Kt = Kg + (size_t)kt * 64 * HS;
        const float* Vt = Vg + (size_t)kt * 64 * HS;

        // ---- load K (transposed) and V (natural) tiles ----
        {
            int r  = tid & 63;
            int cb = tid >> 6;
#pragma unroll
            for (int t = 0; t < 4; t++) {
                int c4 = cb + 4 * t;
                float4 kv = *(const float4*)&Kt[(size_t)r * HS + 4 * c4];
                Kst[(4 * c4 + 0) * 64 + r] = kv.x;
                Kst[(4 * c4 + 1) * 64 + r] = kv.y;
                Kst[(4 * c4 + 2) * 64 + r] = kv.z;
                Kst[(4 * c4 + 3) * 64 + r] = kv.w;
                float4 vv = *(const float4*)&Vt[(size_t)r * HS + 4 * c4];
                *(float4*)&Vs[r * QSTRIDE + 4 * c4] = vv;
            }
        }
        __syncthreads();

        // ---- S = Q @ K^T, h chunked by 2 ----
        float s[4][4];
#pragma unroll
        for (int i = 0; i < 4; i++)
#pragma unroll
            for (int j = 0; j < 4; j++) s[i][j] = 0.0f;

#pragma unroll 4
        for (int h = 0; h < 64; h += 2) {
            float4 b0 = *(const float4*)&Kst[h * 64 + 4 * tx];
            float4 b1 = *(const float4*)&Kst[(h + 1) * 64 + 4 * tx];
            float2 a0 = *(const float2*)&Qs[(4 * ty + 0) * QSTRIDE + h];
            float2 a1 = *(const float2*)&Qs[(4 * ty + 1) * QSTRIDE + h];
            float2 a2 = *(const float2*)&Qs[(4 * ty + 2) * QSTRIDE + h];
            float2 a3 = *(const float2*)&Qs[(4 * ty + 3) * QSTRIDE + h];
            s[0][0] = fmaf(a0.x, b0.x, s[0][0]); s[0][1] = fmaf(a0.x, b0.y, s[0][1]);
            s[0][2] = fmaf(a0.x, b0.z, s[0][2]); s[0][3] = fmaf(a0.x, b0.w, s[0][3]);
            s[1][0] = fmaf(a1.x, b0.x, s[1][0]); s[1][1] = fmaf(a1.x, b0.y, s[1][1]);
            s[1][2] = fmaf(a1.x, b0.z, s[1][2]); s[1][3] = fmaf(a1.x, b0.w, s[1][3]);
            s[2][0] = fmaf(a2.x, b0.x, s[2][0]); s[2][1] = fmaf(a2.x, b0.y, s[2][1]);
            s[2][2] = fmaf(a2.x, b0.z, s[2][2]); s[2][3] = fmaf(a2.x, b0.w, s[2][3]);
            s[3][0] = fmaf(a3.x, b0.x, s[3][0]); s[3][1] = fmaf(a3.x, b0.y, s[3][1]);
            s[3][2] = fmaf(a3.x, b0.z, s[3][2]); s[3][3] = fmaf(a3.x, b0.w, s[3][3]);
            s[0][0] = fmaf(a0.y, b1.x, s[0][0]); s[0][1] = fmaf(a0.y, b1.y, s[0][1]);
            s[0][2] = fmaf(a0.y, b1.z, s[0][2]); s[0][3] = fmaf(a0.y, b1.w, s[0][3]);
            s[1][0] = fmaf(a1.y, b1.x, s[1][0]); s[1][1] = fmaf(a1.y, b1.y, s[1][1]);
            s[1][2] = fmaf(a1.y, b1.z, s[1][2]); s[1][3] = fmaf(a1.y, b1.w, s[1][3]);
            s[2][0] = fmaf(a2.y, b1.x, s[2][0]); s[2][1] = fmaf(a2.y, b1.y, s[2][1]);
            s[2][2] = fmaf(a2.y, b1.z, s[2][2]); s[2][3] = fmaf(a2.y, b1.w, s[2][3]);
            s[3][0] = fmaf(a3.y, b1.x, s[3][0]); s[3][1] = fmaf(a3.y, b1.y, s[3][1]);
            s[3][2] = fmaf(a3.y, b1.z, s[3][2]); s[3][3] = fmaf(a3.y, b1.w, s[3][3]);
        }

        // ---- causal mask on the diagonal tile ----
        if (kt == qt) {
#pragma unroll
            for (int i = 0; i < 4; i++)
#pragma unroll
                for (int j = 0; j < 4; j++)
                    if (4 * tx + j > 4 * ty + i) s[i][j] = -1e30f;
        }

        // ---- online softmax (rows reduced across the 16 tx lanes) ----
#pragma unroll
        for (int i = 0; i < 4; i++) {
            float mx = fmaxf(fmaxf(s[i][0], s[i][1]), fmaxf(s[i][2], s[i][3]));
#pragma unroll
            for (int off = 1; off < 16; off <<= 1)
                mx = fmaxf(mx, __shfl_xor_sync(0xffffffffu, mx, off));
            float mnew = fmaxf(m_[i], mx);
            float alpha = __expf(m_[i] - mnew);
            m_[i] = mnew;
            float ps = 0.0f;
#pragma unroll
            for (int j = 0; j < 4; j++) {
                s[i][j] = __expf(s[i][j] - mnew);
                ps += s[i][j];
            }
#pragma unroll
            for (int off = 1; off < 16; off <<= 1)
                ps += __shfl_xor_sync(0xffffffffu, ps, off);
            l_[i] = l_[i] * alpha + ps;
#pragma unroll
            for (int j = 0; j < 4; j++) o[i][j] *= alpha;
        }

        // ---- publish P tile ----
#pragma unroll
        for (int i = 0; i < 4; i++) {
            float4 pv = make_float4(s[i][0], s[i][1], s[i][2], s[i][3]);
            *(float4*)&Ps[(4 * ty + i) * QSTRIDE + 4 * tx] = pv;
        }
        __syncthreads();

        // ---- O += P @ V, j chunked by 2 ----
#pragma unroll 4
        for (int j = 0; j < 64; j += 2) {
            float4 v0 = *(const float4*)&Vs[j * QSTRIDE + 4 * tx];
            float4 v1 = *(const float4*)&Vs[(j + 1) * QSTRIDE + 4 * tx];
            float2 p0 = *(const float2*)&Ps[(4 * ty + 0) * QSTRIDE + j];
            float2 p1 = *(const float2*)&Ps[(4 * ty + 1) * QSTRIDE + j];
            float2 p2 = *(const float2*)&Ps[(4 * ty + 2) * QSTRIDE + j];
            float2 p3 = *(const float2*)&Ps[(4 * ty + 3) * QSTRIDE + j];
            o[0][0] = fmaf(p0.x, v0.x, o[0][0]); o[0][1] = fmaf(p0.x, v0.y, o[0][1]);
            o[0][2] = fmaf(p0.x, v0.z, o[0][2]); o[0][3] = fmaf(p0.x, v0.w, o[0][3]);
            o[1][0] = fmaf(p1.x, v0.x, o[1][0]); o[1][1] = fmaf(p1.x, v0.y, o[1][1]);
            o[1][2] = fmaf(p1.x, v0.z, o[1][2]); o[1][3] = fmaf(p1.x, v0.w, o[1][3]);
            o[2][0] = fmaf(p2.x, v0.x, o[2][0]); o[2][1] = fmaf(p2.x, v0.y, o[2][1]);
            o[2][2] = fmaf(p2.x, v0.z, o[2][2]); o[2][3] = fmaf(p2.x, v0.w, o[2][3]);
            o[3][0] = fmaf(p3.x, v0.x, o[3][0]); o[3][1] = fmaf(p3.x, v0.y, o[3][1]);
            o[3][2] = fmaf(p3.x, v0.z, o[3][2]); o[3][3] = fmaf(p3.x, v0.w, o[3][3]);
            o[0][0] = fmaf(p0.y, v1.x, o[0][0]); o[0][1] = fmaf(p0.y, v1.y, o[0][1]);
            o[0][2] = fmaf(p0.y, v1.z, o[0][2]); o[0][3] = fmaf(p0.y, v1.w, o[0][3]);
            o[1][0] = fmaf(p1.y, v1.x, o[1][0]); o[1][1] = fmaf(p1.y, v1.y, o[1][1]);
            o[1][2] = fmaf(p1.y, v1.z, o[1][2]); o[1][3] = fmaf(p1.y, v1.w, o[1][3]);
            o[2][0] = fmaf(p2.y, v1.x, o[2][0]); o[2][1] = fmaf(p2.y, v1.y, o[2][1]);
            o[2][2] = fmaf(p2.y, v1.z, o[2][2]); o[2][3] = fmaf(p2.y, v1.w, o[2][3]);
            o[3][0] = fmaf(p3.y, v1.x, o[3][0]); o[3][1] = fmaf(p3.y, v1.y, o[3][1]);
            o[3][2] = fmaf(p3.y, v1.z, o[3][2]); o[3][3] = fmaf(p3.y, v1.w, o[3][3]);
        }
        __syncthreads();
    }

    // ---- write partial (unnormalized O, row max m, row sum l) ----
    const size_t slot = (size_t)b * NBLK + l;
    float* PO = g_po + slot * 64 * HS;
#pragma unroll
    for (int i = 0; i < 4; i++) {
        float4 ov = make_float4(o[i][0], o[i][1], o[i][2], o[i][3]);
        *(float4*)&PO[(size_t)(4 * ty + i) * HS + 4 * tx] = ov;
    }
    if (tx == 0) {
#pragma unroll
        for (int i = 0; i < 4; i++) {
            g_pm[slot * 64 + 4 * ty + i] = m_[i];
            g_pl[slot * 64 + 4 * ty + i] = l_[i];
        }
    }
}

// ---------------------------------------------------------------------------
// Kernel 3: combine partials (log-sum-exp merge) + epilogue /(l*8).
// Grid (NQT, BATCH), 256 threads: thread = (row r = tid>>2, colgroup tid&3
// covering 16 cols).
// ---------------------------------------------------------------------------
__global__ __launch_bounds__(256) void attn_reduce_kernel(float* __restrict__ out)
{
    const int b  = blockIdx.y;
    const int qt = blockIdx.x;
    const int tid = threadIdx.x;
    const int r  = tid >> 2;
    const int cg = (tid & 3) * 16;

    const int nch = qt / CHUNK + 1;   // number of partial chunks for this qt

    // pass 1: global row max
    float m = -1e30f;
    for (int c = 0; c < nch; c++) {
        int base = 66 * c - 2 * c * c;             // prefix P_c
        size_t slot = (size_t)b * NBLK + base + (qt - 4 * c);
        m = fmaxf(m, g_pm[slot * 64 + r]);
    }

    // pass 2: weighted combine
    float lsum = 0.0f;
    float acc[16];
#pragma unroll
    for (int t = 0; t < 16; t++) acc[t] = 0.0f;

    for (int c = 0; c < nch; c++) {
        int base = 66 * c - 2 * c * c;
        size_t slot = (size_t)b * NBLK + base + (qt - 4 * c);
        float w = __expf(g_pm[slot * 64 + r] - m);
        lsum = fmaf(w, g_pl[slot * 64 + r], lsum);
        const float* PO = g_po + (slot * 64 + r) * HS + cg;
#pragma unroll
        for (int t = 0; t < 4; t++) {
            float4 v = *(const float4*)&PO[4 * t];
            acc[4 * t + 0] = fmaf(w, v.x, acc[4 * t + 0]);
            acc[4 * t + 1] = fmaf(w, v.y, acc[4 * t + 1]);
            acc[4 * t + 2] = fmaf(w, v.z, acc[4 * t + 2]);
            acc[4 * t + 3] = fmaf(w, v.w, acc[4 * t + 3]);
        }
    }

    // epilogue: /(l) for softmax and /8 for the reference's post-softmax
    // divide-by-sqrt(head_size) quirk (linear in V, folded here)
    const float inv = 1.0f / (lsum * 8.0f);
    float* O = out + ((size_t)b * TSEQ + qt * 64 + r) * HS + cg;
#pragma unroll
    for (int t = 0; t < 4; t++) {
        float4 v = make_float4(acc[4 * t + 0] * inv, acc[4 * t + 1] * inv,
                               acc[4 * t + 2] * inv, acc[4 * t + 3] * inv);
        *(float4*)&O[4 * t] = v;
    }
}

// ---------------------------------------------------------------------------
extern "C" void kernel_launch(void* const* d_in, const int* in_sizes, int n_in,
                              void* d_out, int out_size)
{
    const float* X  = (const float*)d_in[0];
    const float* Wq = (const float*)d_in[1];
    const float* Wk = (const float*)d_in[2];
    const float* Wv = (const float*)d_in[3];
    float* out = (float*)d_out;

    (void)in_sizes; (void)n_in; (void)out_size;

    // QKV projection: grid (16384/128, 3)
    dim3 g1(MTOT / 128, 3);
    qkv_kernel<<<g1, 256>>>(X, Wq, Wk, Wv);

    // Flash attention partials: grid (544 chunk-blocks, 4 batches)
    cudaFuncSetAttribute(attn_partial_kernel,
                         cudaFuncAttributeMaxDynamicSharedMemorySize, SMEM_BYTES);
    dim3 g2(NBLK, BATCH);
    attn_partial_kernel<<<g2, 256, SMEM_BYTES>>>();

    // Combine partials + epilogue
    dim3 g3(NQT, BATCH);
    attn_reduce_kernel<<<g3, 256>>>(out);
}

// round 6
// speedup vs baseline: 1.4436x; 1.4436x over previous
#include <cuda_runtime.h>
#include <math.h>
#include <stdint.h>

#define EMB   1024
#define HS    64
#define TSEQ  4096
#define BATCH 4
#define MTOT  (BATCH * TSEQ)   // 16384 rows

#define NQT    64              // 64-row q tiles per batch
#define CHUNK  16              // kv-tiles per partial block
#define NBLK   160             // sum_{c=0..3} (64-16c) blocks per batch

// Scratch (device globals: allocation-free rule)
__device__ float g_q[MTOT * HS];
__device__ float g_k[MTOT * HS];
__device__ float g_v[MTOT * HS];
__device__ float g_po[BATCH * NBLK * 64 * HS];   // partial O (unnormalized)
__device__ float g_pm[BATCH * NBLK * 64];        // partial row max
__device__ float g_pl[BATCH * NBLK * 64];        // partial row sum

// ---- packed fp32x2 ops (Blackwell FFMA2 path; exact fp32 per lane) ----
#define FMA2(d, a, b) \
    asm("fma.rn.f32x2 %0, %1, %2, %0;" : "+l"(d) : "l"(a), "l"(b))
#define MUL2(d, a) \
    asm("mul.rn.f32x2 %0, %0, %1;" : "+l"(d) : "l"(a))
#define PACK2(d, x) \
    asm("mov.b64 %0, {%1, %1};" : "=l"(d) : "r"(__float_as_uint(x)))
#define UNPACK2(x, y, d) do { \
    unsigned _lo, _hi; \
    asm("mov.b64 {%0, %1}, %2;" : "=r"(_lo), "=r"(_hi) : "l"(d)); \
    (x) = __uint_as_float(_lo); (y) = __uint_as_float(_hi); } while (0)

// ---------------------------------------------------------------------------
// Kernel 1: fused QKV projection.  [q|k|v] = X @ [Wq|Wk|Wv].
// BM=64 rows, BN=3x64 cols, BK=32. 128 threads; each thread owns an
// 8-row x (3 x 4-col) microtile on packed f32x2 accumulators.
// X tile stored naturally [64][33] (pad 1: conflict-free scalar access);
// W tiles [32][68] (pad: conflict-free STS + aligned ulonglong2 loads).
// ---------------------------------------------------------------------------
#define XST 33
#define WST 68

__global__ __launch_bounds__(128) void qkv_kernel(
    const float* __restrict__ X,
    const float* __restrict__ Wq,
    const float* __restrict__ Wk,
    const float* __restrict__ Wv)
{
    __shared__ __align__(16) float Xs[64 * XST];       // [row][k]
    __shared__ __align__(16) float Ws[3][32 * WST];    // [w][k][col]

    const int tid = threadIdx.x;
    const int tx = tid & 15;        // col group: cols 4*tx..4*tx+3 (per W)
    const int ty = tid >> 4;        // 0..7 -> rows 8*ty..8*ty+7
    const int m0 = blockIdx.x * 64;

    // X load mapping (coalesced): 8 threads cover one row's 128B chunk
    const int lr8 = tid >> 3;       // 0..15 base row
    const int lc8 = tid & 7;        // 0..7 float4 col group within BK=32
    // W load mapping
    const int wr  = tid >> 2;       // 0..31 k-row
    const int wc4 = tid & 3;        // 0..3 -> col groups wc4 + 4t

    const float* Wp0 = Wq; const float* Wp1 = Wk; const float* Wp2 = Wv;

    unsigned long long acc[3][8][2];
#pragma unroll
    for (int w = 0; w < 3; w++)
#pragma unroll
        for (int i = 0; i < 8; i++) { acc[w][i][0] = 0ull; acc[w][i][1] = 0ull; }

    for (int k0 = 0; k0 < EMB; k0 += 32) {
        // X tile 64x32 (natural layout, scalar stores conflict-free)
#pragma unroll
        for (int t = 0; t < 4; t++) {
            int row = lr8 + 16 * t;
            float4 xv = *(const float4*)&X[(size_t)(m0 + row) * EMB + k0 + 4 * lc8];
            Xs[row * XST + 4 * lc8 + 0] = xv.x;
            Xs[row * XST + 4 * lc8 + 1] = xv.y;
            Xs[row * XST + 4 * lc8 + 2] = xv.z;
            Xs[row * XST + 4 * lc8 + 3] = xv.w;
        }
        // W tiles 32x64 each
#pragma unroll
        for (int t = 0; t < 4; t++) {
            int cg = wc4 + 4 * t;    // 0..15
            *(float4*)&Ws[0][wr * WST + 4 * cg] =
                *(const float4*)&Wp0[(size_t)(k0 + wr) * HS + 4 * cg];
            *(float4*)&Ws[1][wr * WST + 4 * cg] =
                *(const float4*)&Wp1[(size_t)(k0 + wr) * HS + 4 * cg];
            *(float4*)&Ws[2][wr * WST + 4 * cg] =
                *(const float4*)&Wp2[(size_t)(k0 + wr) * HS + 4 * cg];
        }
        __syncthreads();

#pragma unroll 4
        for (int kk = 0; kk < 32; kk++) {
            unsigned long long ap[8];
#pragma unroll
            for (int i = 0; i < 8; i++) {
                float a = Xs[(8 * ty + i) * XST + kk];    // broadcast scalar LDS
                PACK2(ap[i], a);
            }
            ulonglong2 b0 = *(const ulonglong2*)&Ws[0][kk * WST + 4 * tx];
            ulonglong2 b1 = *(const ulonglong2*)&Ws[1][kk * WST + 4 * tx];
            ulonglong2 b2 = *(const ulonglong2*)&Ws[2][kk * WST + 4 * tx];
#pragma unroll
            for (int i = 0; i < 8; i++) {
                FMA2(acc[0][i][0], ap[i], b0.x); FMA2(acc[0][i][1], ap[i], b0.y);
                FMA2(acc[1][i][0], ap[i], b1.x); FMA2(acc[1][i][1], ap[i], b1.y);
                FMA2(acc[2][i][0], ap[i], b2.x); FMA2(acc[2][i][1], ap[i], b2.y);
            }
        }
        __syncthreads();
    }

#pragma unroll
    for (int i = 0; i < 8; i++) {
        size_t row = (size_t)(m0 + 8 * ty + i);
        *(ulonglong2*)&g_q[row * HS + 4 * tx] = make_ulonglong2(acc[0][i][0], acc[0][i][1]);
        *(ulonglong2*)&g_k[row * HS + 4 * tx] = make_ulonglong2(acc[1][i][0], acc[1][i][1]);
        *(ulonglong2*)&g_v[row * HS + 4 * tx] = make_ulonglong2(acc[2][i][0], acc[2][i][1]);
    }
}

// ---------------------------------------------------------------------------
// Kernel 2: split-KV flash attention partials, packed f32x2 math.
// Each block: one 64-row q-tile x up to CHUNK(=16) kv-tiles.
// Block map (per batch): chunk c in 0..3, base(c) = 64c - 8c(c-1)
// (= 0,64,112,144), qt = 63 - (l - base)  [LPT: big jobs first].
// 256 threads = 16x16; 4x4 microtile (as 4x2 packed pairs).
// ---------------------------------------------------------------------------
#define QSTRIDE 68
#define SMEM_FLOATS (64 * QSTRIDE /*Qs*/ + 64 * 64 /*Kst*/ + 64 * QSTRIDE /*Vs*/ + 64 * QSTRIDE /*Ps*/)
#define SMEM_BYTES (SMEM_FLOATS * 4)

__global__ __launch_bounds__(256) void attn_partial_kernel(void)
{
    extern __shared__ __align__(16) float sm[];
    float* Qs  = sm;                       // [64][68] natural
    float* Kst = Qs  + 64 * QSTRIDE;       // [64][64] transposed: Kst[h][j]
    float* Vs  = Kst + 64 * 64;            // [64][68] natural
    float* Ps  = Vs  + 64 * QSTRIDE;       // [64][68] natural

    const int b = blockIdx.y;
    const int l = blockIdx.x;

    int c, idx;
    if      (l < 64)  { c = 0; idx = l; }
    else if (l < 112) { c = 1; idx = l - 64; }
    else if (l < 144) { c = 2; idx = l - 112; }
    else              { c = 3; idx = l - 144; }
    const int qt  = 63 - idx;              // descending size (LPT)
    const int kt0 = 16 * c;
    const int kt1 = min(16 * c + CHUNK, qt + 1);

    const int tid = threadIdx.x;
    const int tx = tid & 15;
    const int ty = tid >> 4;

    const float* Qg = g_q + ((size_t)b * TSEQ + qt * 64) * HS;
    const float* Kg = g_k + (size_t)b * TSEQ * HS;
    const float* Vg = g_v + (size_t)b * TSEQ * HS;

    // ---- load Q tile (once) ----
    {
        int r  = tid & 63;
        int cb = tid >> 6;
#pragma unroll
        for (int t = 0; t < 4; t++) {
            int c4 = cb + 4 * t;
            float4 v = *(const float4*)&Qg[(size_t)r * HS + 4 * c4];
            *(float4*)&Qs[r * QSTRIDE + 4 * c4] = v;
        }
    }

    float m_[4], l_[4];
    unsigned long long o2[4][2];
#pragma unroll
    for (int i = 0; i < 4; i++) {
        m_[i] = -1e30f; l_[i] = 0.0f;
        o2[i][0] = 0ull; o2[i][1] = 0ull;
    }

    for (int kt = kt0; kt < kt1; kt++) {
        const float* Kt = Kg + (size_t)kt * 64 * HS;
        const float* Vt = Vg + (size_t)kt * 64 * HS;

        // ---- load K (transposed) and V (natural) tiles ----
        {
            int r  = tid & 63;
            int cb = tid >> 6;
#pragma unroll
            for (int t = 0; t < 4; t++) {
                int c4 = cb + 4 * t;
                float4 kv = *(const float4*)&Kt[(size_t)r * HS + 4 * c4];
                Kst[(4 * c4 + 0) * 64 + r] = kv.x;
                Kst[(4 * c4 + 1) * 64 + r] = kv.y;
                Kst[(4 * c4 + 2) * 64 + r] = kv.z;
                Kst[(4 * c4 + 3) * 64 + r] = kv.w;
                float4 vv = *(const float4*)&Vt[(size_t)r * HS + 4 * c4];
                *(float4*)&Vs[r * QSTRIDE + 4 * c4] = vv;
            }
        }
        __syncthreads();

        // ---- S = Q @ K^T (packed: 8 FFMA2 per h) ----
        unsigned long long s2[4][2];
#pragma unroll
        for (int i = 0; i < 4; i++) { s2[i][0] = 0ull; s2[i][1] = 0ull; }

#pragma unroll 4
        for (int h = 0; h < 64; h++) {
            ulonglong2 bb = *(const ulonglong2*)&Kst[h * 64 + 4 * tx];
            unsigned long long ap;
            float a0 = Qs[(4 * ty + 0) * QSTRIDE + h];
            PACK2(ap, a0); FMA2(s2[0][0], ap, bb.x); FMA2(s2[0][1], ap, bb.y);
            float a1 = Qs[(4 * ty + 1) * QSTRIDE + h];
            PACK2(ap, a1); FMA2(s2[1][0], ap, bb.x); FMA2(s2[1][1], ap, bb.y);
            float a2 = Qs[(4 * ty + 2) * QSTRIDE + h];
            PACK2(ap, a2); FMA2(s2[2][0], ap, bb.x); FMA2(s2[2][1], ap, bb.y);
            float a3 = Qs[(4 * ty + 3) * QSTRIDE + h];
            PACK2(ap, a3); FMA2(s2[3][0], ap, bb.x); FMA2(s2[3][1], ap, bb.y);
        }

        // ---- unpack ----
        float s[4][4];
#pragma unroll
        for (int i = 0; i < 4; i++) {
            UNPACK2(s[i][0], s[i][1], s2[i][0]);
            UNPACK2(s[i][2], s[i][3], s2[i][1]);
        }

        // ---- causal mask on the diagonal tile ----
        if (kt == qt) {
#pragma unroll
            for (int i = 0; i < 4; i++)
#pragma unroll
                for (int j = 0; j < 4; j++)
                    if (4 * tx + j > 4 * ty + i) s[i][j] = -1e30f;
        }

        // ---- online softmax (rows reduced across the 16 tx lanes) ----
#pragma unroll
        for (int i = 0; i < 4; i++) {
            float mx = fmaxf(fmaxf(s[i][0], s[i][1]), fmaxf(s[i][2], s[i][3]));
#pragma unroll
            for (int off = 1; off < 16; off <<= 1)
                mx = fmaxf(mx, __shfl_xor_sync(0xffffffffu, mx, off));
            float mnew = fmaxf(m_[i], mx);
            float alpha = __expf(m_[i] - mnew);
            m_[i] = mnew;
            float ps = 0.0f;
#pragma unroll
            for (int j = 0; j < 4; j++) {
                s[i][j] = __expf(s[i][j] - mnew);
                ps += s[i][j];
            }
#pragma unroll
            for (int off = 1; off < 16; off <<= 1)
                ps += __shfl_xor_sync(0xffffffffu, ps, off);
            l_[i] = l_[i] * alpha + ps;
            unsigned long long al2;
            PACK2(al2, alpha);
            MUL2(o2[i][0], al2);
            MUL2(o2[i][1], al2);
        }

        // ---- publish P tile ----
#pragma unroll
        for (int i = 0; i < 4; i++) {
            float4 pv = make_float4(s[i][0], s[i][1], s[i][2], s[i][3]);
            *(float4*)&Ps[(4 * ty + i) * QSTRIDE + 4 * tx] = pv;
        }
        __syncthreads();

        // ---- O += P @ V (packed) ----
#pragma unroll 4
        for (int j = 0; j < 64; j++) {
            ulonglong2 vv = *(const ulonglong2*)&Vs[j * QSTRIDE + 4 * tx];
            unsigned long long pp;
            float p0 = Ps[(4 * ty + 0) * QSTRIDE + j];
            PACK2(pp, p0); FMA2(o2[0][0], pp, vv.x); FMA2(o2[0][1], pp, vv.y);
            float p1 = Ps[(4 * ty + 1) * QSTRIDE + j];
            PACK2(pp, p1); FMA2(o2[1][0], pp, vv.x); FMA2(o2[1][1], pp, vv.y);
            float p2 = Ps[(4 * ty + 2) * QSTRIDE + j];
            PACK2(pp, p2); FMA2(o2[2][0], pp, vv.x); FMA2(o2[2][1], pp, vv.y);
            float p3 = Ps[(4 * ty + 3) * QSTRIDE + j];
            PACK2(pp, p3); FMA2(o2[3][0], pp, vv.x); FMA2(o2[3][1], pp, vv.y);
        }
        __syncthreads();
    }

    // ---- write partial (unnormalized O, row max m, row sum l) ----
    const size_t slot = (size_t)b * NBLK + l;
    float* PO = g_po + slot * 64 * HS;
#pragma unroll
    for (int i = 0; i < 4; i++)
        *(ulonglong2*)&PO[(size_t)(4 * ty + i) * HS + 4 * tx] =
            make_ulonglong2(o2[i][0], o2[i][1]);
    if (tx == 0) {
#pragma unroll
        for (int i = 0; i < 4; i++) {
            g_pm[slot * 64 + 4 * ty + i] = m_[i];
            g_pl[slot * 64 + 4 * ty + i] = l_[i];
        }
    }
}

// ---------------------------------------------------------------------------
// Kernel 3: combine partials (log-sum-exp merge) + epilogue /(l*8).
// Grid (NQT, BATCH), 256 threads: row r = tid>>2, colgroup (tid&3)*16.
// slot for (qt, c): base(c) + (63 - qt), base(c) = 64c - 8c(c-1).
// ---------------------------------------------------------------------------
__global__ __launch_bounds__(256) void attn_reduce_kernel(float* __restrict__ out)
{
    const int b  = blockIdx.y;
    const int qt = blockIdx.x;
    const int tid = threadIdx.x;
    const int r  = tid >> 2;
    const int cg = (tid & 3) * 16;

    const int nch = qt / CHUNK + 1;

    // pass 1: global row max
    float m = -1e30f;
    for (int c = 0; c < nch; c++) {
        int base = 64 * c - 8 * c * (c - 1);
        size_t slot = (size_t)b * NBLK + base + (63 - qt);
        m = fmaxf(m, g_pm[slot * 64 + r]);
    }

    // pass 2: weighted combine
    float lsum = 0.0f;
    float acc[16];
#pragma unroll
    for (int t = 0; t < 16; t++) acc[t] = 0.0f;

    for (int c = 0; c < nch; c++) {
        int base = 64 * c - 8 * c * (c - 1);
        size_t slot = (size_t)b * NBLK + base + (63 - qt);
        float w = __expf(g_pm[slot * 64 + r] - m);
        lsum = fmaf(w, g_pl[slot * 64 + r], lsum);
        const float* PO = g_po + (slot * 64 + r) * HS + cg;
#pragma unroll
        for (int t = 0; t < 4; t++) {
            float4 v = *(const float4*)&PO[4 * t];
            acc[4 * t + 0] = fmaf(w, v.x, acc[4 * t + 0]);
            acc[4 * t + 1] = fmaf(w, v.y, acc[4 * t + 1]);
            acc[4 * t + 2] = fmaf(w, v.z, acc[4 * t + 2]);
            acc[4 * t + 3] = fmaf(w, v.w, acc[4 * t + 3]);
        }
    }

    // /(l) for softmax, /8 for the reference's post-softmax /sqrt(HS) quirk
    const float inv = 1.0f / (lsum * 8.0f);
    float* O = out + ((size_t)b * TSEQ + qt * 64 + r) * HS + cg;
#pragma unroll
    for (int t = 0; t < 4; t++) {
        float4 v = make_float4(acc[4 * t + 0] * inv, acc[4 * t + 1] * inv,
                               acc[4 * t + 2] * inv, acc[4 * t + 3] * inv);
        *(float4*)&O[4 * t] = v;
    }
}

// ---------------------------------------------------------------------------
extern "C" void kernel_launch(void* const* d_in, const int* in_sizes, int n_in,
                              void* d_out, int out_size)
{
    const float* X  = (const float*)d_in[0];
    const float* Wq = (const float*)d_in[1];
    const float* Wk = (const float*)d_in[2];
    const float* Wv = (const float*)d_in[3];
    float* out = (float*)d_out;

    (void)in_sizes; (void)n_in; (void)out_size;

    // Fused QKV projection: 256 blocks x 128 threads
    qkv_kernel<<<MTOT / 64, 128>>>(X, Wq, Wk, Wv);

    // Flash attention partials: (160 chunk-blocks, 4 batches)
    cudaFuncSetAttribute(attn_partial_kernel,
                         cudaFuncAttributeMaxDynamicSharedMemorySize, SMEM_BYTES);
    dim3 g2(NBLK, BATCH);
    attn_partial_kernel<<<g2, 256, SMEM_BYTES>>>();

    // Combine partials + epilogue
    dim3 g3(NQT, BATCH);
    attn_reduce_kernel<<<g3, 256>>>(out);
}